// round 5
// baseline (speedup 1.0000x reference)
#include <cuda_runtime.h>
#include <cuda_bf16.h>
#include <math.h>

// ContrastiveLoss: N=8192 points, D=64, labels int32 in [0,8).
// loss = [ sum_{same-label,i!=j} d2  +  sum_{diff-label} max(1-d,0)^2 ] / (N*(N-1))
//
//   pos term: exact closed form per class: sum d2 = 2*(n_c*S2_c - |S1_c|^2)  (O(N*D))
//   neg term: nonzero only when d < 1. 8-dim partial distance (dot form) is an exact
//             lower bound on d2 -> screen all pairs with packed f32x2 FMAs,
//             inline-evaluate rare survivors on all 64 dims.

#define N_PTS 8192
#define NDIM  64
#define NCLS  8
#define TI    512     // i-rows per screen block (4 per thread)
#define TJ    128     // j-rows per screen block

__device__ float  g_s1[NCLS * NDIM];   // per-class vector sums (RED.ADD targets)
__device__ float  g_s2[NCLS * NDIM];   // per-class per-dim sum of squares
__device__ double g_neg;

typedef unsigned long long u64;

#define FFMA2(d, a, b, c) \
    asm("fma.rn.f32x2 %0, %1, %2, %3;" : "=l"(d) : "l"(a), "l"(b), "l"(c))
#define PACK2(out, f) do {                                            \
    unsigned _u = __float_as_uint(f);                                 \
    asm("mov.b64 %0, {%1, %2};" : "=l"(out) : "r"(_u), "r"(_u));      \
} while (0)
#define UNPACK2(lo, hi, v) \
    asm("mov.b64 {%0, %1}, %2;" : "=f"(lo), "=f"(hi) : "l"(v))

// ---------------- K0: zero accumulators ----------------
__global__ void zero_kernel() {
    int t = threadIdx.x;
    g_s1[t] = 0.0f;
    g_s2[t] = 0.0f;
    if (t == 0) g_neg = 0.0;
}

// ---------------- K1: prep (per-class sums via register accum + RED.ADD) ------
// grid 512 x 64 threads. Block b: rows [b*16, b*16+16). Thread k = dimension.
__global__ void __launch_bounds__(64) prep_kernel(const float* __restrict__ X,
                                                  const int* __restrict__ lab) {
    int k  = threadIdx.x;
    int r0 = blockIdx.x * 16;

    __shared__ int slab[16];
    if (k < 16) slab[k] = lab[r0 + k];
    __syncthreads();

    float a1[NCLS], a2[NCLS];
#pragma unroll
    for (int c = 0; c < NCLS; c++) { a1[c] = 0.0f; a2[c] = 0.0f; }
#pragma unroll
    for (int rr = 0; rr < 16; ++rr) {
        float v  = X[(r0 + rr) * NDIM + k];
        float v2 = v * v;
        int   c  = slab[rr];
#pragma unroll
        for (int cc = 0; cc < NCLS; cc++) {
            bool m = (cc == c);
            a1[cc] += m ? v  : 0.0f;
            a2[cc] += m ? v2 : 0.0f;
        }
    }
#pragma unroll
    for (int cc = 0; cc < NCLS; cc++) {
        atomicAdd(&g_s1[cc * NDIM + k], a1[cc]);
        atomicAdd(&g_s2[cc * NDIM + k], a2[cc]);
    }
}

// ---------------- rare path: exact 64-dim evaluation ----------------
__device__ __noinline__ void eval_pair(const float* __restrict__ X,
                                       const int* __restrict__ lab, int i, int j) {
    if (j <= i) return;                 // diagonal-region duplicates
    if (lab[i] == lab[j]) return;       // same-label handled in closed form
    const float4* xi = (const float4*)(X + i * NDIM);
    const float4* xj = (const float4*)(X + j * NDIM);
    float s = 0.0f;
#pragma unroll
    for (int q = 0; q < 16; q++) {
        float4 a = xi[q], b = xj[q];
        float d;
        d = a.x - b.x; s = fmaf(d, d, s);
        d = a.y - b.y; s = fmaf(d, d, s);
        d = a.z - b.z; s = fmaf(d, d, s);
        d = a.w - b.w; s = fmaf(d, d, s);
    }
    if (s < 1.0f) {
        float u = 1.0f - sqrtf(fmaxf(s, 0.0f));
        atomicAdd(&g_neg, 2.0 * (double)u * (double)u);   // unordered -> ordered pairs
    }
}

__device__ __forceinline__ float half_norm8(float4 v0, float4 v1) {
    float s = v0.x * v0.x;
    s = fmaf(v0.y, v0.y, s);
    s = fmaf(v0.z, v0.z, s);
    s = fmaf(v0.w, v0.w, s);
    s = fmaf(v1.x, v1.x, s);
    s = fmaf(v1.y, v1.y, s);
    s = fmaf(v1.z, v1.z, s);
    s = fmaf(v1.w, v1.w, s);
    return 0.5f * s;
}

// ---------------- K2: screen (8-dim lower bound, f32x2-packed) ----------------
// grid (64, 16), 128 threads. Block (bj,bi): i in [bi*512,+512), j in [bj*128,+128).
// Keep blocks that can contain j > i pairs: bj >= 4*bi.
// Pass test: (dot8 - hj) > hi - 0.505  <=>  8-dim partial d2 < 1.01 (exact LB on d2).
__global__ void __launch_bounds__(128, 3) screen_kernel(const float* __restrict__ X,
                                                        const int* __restrict__ lab) {
    int bi = blockIdx.y, bj = blockIdx.x;
    if (bj < 4 * bi) return;
    int t = threadIdx.x;

    __shared__ __align__(16) float sb[8][TJ];   // dim-major j tile
    __shared__ __align__(16) float smh[TJ];     // -hj
    const float4* Xv = (const float4*)X;

    {
        int jr = bj * TJ + t;
        float4 j0 = Xv[jr * 16 + 0];
        float4 j1 = Xv[jr * 16 + 1];
        sb[0][t] = j0.x; sb[1][t] = j0.y; sb[2][t] = j0.z; sb[3][t] = j0.w;
        sb[4][t] = j1.x; sb[5][t] = j1.y; sb[6][t] = j1.z; sb[7][t] = j1.w;
        smh[t]   = -half_norm8(j0, j1);
    }

    u64   ap[4][8];     // splatted i-row components
    float ci[4];
    int   ib[4];
#pragma unroll
    for (int r = 0; r < 4; r++) {
        ib[r] = bi * TI + r * 128 + t;
        float4 a0 = Xv[ib[r] * 16 + 0];
        float4 a1 = Xv[ib[r] * 16 + 1];
        ci[r] = half_norm8(a0, a1) - 0.505f;
        PACK2(ap[r][0], a0.x); PACK2(ap[r][1], a0.y);
        PACK2(ap[r][2], a0.z); PACK2(ap[r][3], a0.w);
        PACK2(ap[r][4], a1.x); PACK2(ap[r][5], a1.y);
        PACK2(ap[r][6], a1.z); PACK2(ap[r][7], a1.w);
    }
    __syncthreads();

#pragma unroll 4
    for (int j0 = 0; j0 < TJ; j0 += 4) {
        // acc init = (-h[j], -h[j+1]) / (-h[j+2], -h[j+3]), packed straight from smem
        ulonglong2 mh = *(const ulonglong2*)&smh[j0];
        u64 acc[4][2];
#pragma unroll
        for (int r = 0; r < 4; r++) { acc[r][0] = mh.x; acc[r][1] = mh.y; }
#pragma unroll
        for (int d = 0; d < 8; d++) {
            ulonglong2 bb = *(const ulonglong2*)&sb[d][j0];
#pragma unroll
            for (int r = 0; r < 4; r++) {
                FFMA2(acc[r][0], ap[r][d], bb.x, acc[r][0]);
                FFMA2(acc[r][1], ap[r][d], bb.y, acc[r][1]);
            }
        }
        float dd[4][4];
        bool any = false;
#pragma unroll
        for (int r = 0; r < 4; r++) {
            UNPACK2(dd[r][0], dd[r][1], acc[r][0]);
            UNPACK2(dd[r][2], dd[r][3], acc[r][1]);
            any = any | (dd[r][0] > ci[r]) | (dd[r][1] > ci[r])
                      | (dd[r][2] > ci[r]) | (dd[r][3] > ci[r]);
        }
        if (any) {
            int jg0 = bj * TJ + j0;
#pragma unroll
            for (int r = 0; r < 4; r++)
#pragma unroll
                for (int jj = 0; jj < 4; jj++)
                    if (dd[r][jj] > ci[r]) eval_pair(X, lab, ib[r], jg0 + jj);
        }
    }
}

// ---------------- K3: finalize ----------------
__global__ void __launch_bounds__(512) finalize_kernel(const int* __restrict__ lab,
                                                       float* __restrict__ out) {
    int t = threadIdx.x;                    // t = c*64 + k
    __shared__ int    hist[NCLS];
    __shared__ double red[512];

    if (t < NCLS) hist[t] = 0;
    __syncthreads();
    for (int r = t; r < N_PTS; r += 512) atomicAdd(&hist[lab[r]], 1);
    __syncthreads();

    int c = t >> 6;
    double S1 = (double)g_s1[t];
    double S2 = (double)g_s2[t];
    red[t] = (double)hist[c] * S2 - S1 * S1;
    __syncthreads();
    for (int s = 256; s > 0; s >>= 1) {
        if (t < s) red[t] += red[t + s];
        __syncthreads();
    }
    if (t == 0) {
        double pos  = 2.0 * red[0];
        double loss = (pos + g_neg) / ((double)N_PTS * (double)(N_PTS - 1));
        out[0] = (float)loss;
    }
}

extern "C" void kernel_launch(void* const* d_in, const int* in_sizes, int n_in,
                              void* d_out, int out_size) {
    const float* X   = (const float*)d_in[0];
    const int*   lab = (const int*)d_in[1];
    float*       out = (float*)d_out;

    zero_kernel<<<1, 512>>>();
    prep_kernel<<<512, 64>>>(X, lab);
    dim3 g(64, 16);
    screen_kernel<<<g, 128>>>(X, lab);
    finalize_kernel<<<1, 512>>>(lab, out);
}

// round 7
// speedup vs baseline: 3.5662x; 3.5662x over previous
#include <cuda_runtime.h>
#include <cuda_bf16.h>
#include <math.h>

// ContrastiveLoss: N=8192 points, D=64, labels int32 in [0,8).
// loss = [ sum_{same-label,i!=j} d2  +  sum_{diff-label} max(1-d,0)^2 ] / (N*(N-1))
//
//   pos term: exact closed form per class: sum d2 = 2*(n_c*S2_c - |S1_c|^2)  (O(N*D))
//   neg term: nonzero only when d < 1. 8-dim partial distance (dot form) is an exact
//             lower bound on d2 -> screen all pairs, inline-evaluate rare survivors
//             on all 64 dims.

#define N_PTS 8192
#define NDIM  64
#define NCLS  8
#define TI    512     // i-rows per screen block (4 per thread)
#define TJ    128     // j-rows per screen block

__device__ float  g_s1[NCLS * NDIM];   // per-class vector sums (RED.ADD targets)
__device__ float  g_s2[NCLS * NDIM];   // per-class per-dim sum of squares
__device__ double g_neg;

// ---------------- K0: zero accumulators ----------------
__global__ void zero_kernel() {
    int t = threadIdx.x;
    g_s1[t] = 0.0f;
    g_s2[t] = 0.0f;
    if (t == 0) g_neg = 0.0;
}

// ---------------- K1: prep (per-class sums, smem-reduced, then RED.ADD) -------
// grid 128 x 256 threads. Block b: rows [b*64, b*64+64).
// Thread t: k = t&63 (dim), g = t>>6 (row group of 16).
__global__ void __launch_bounds__(256) prep_kernel(const float* __restrict__ X,
                                                   const int* __restrict__ lab) {
    int t  = threadIdx.x;
    int k  = t & 63;
    int g  = t >> 6;
    int r0 = blockIdx.x * 64 + g * 16;

    __shared__ int   slab[64];
    __shared__ float red1[4][NCLS * NDIM];
    __shared__ float red2[4][NCLS * NDIM];
    if (t < 64) slab[t] = lab[blockIdx.x * 64 + t];
    __syncthreads();

    float a1[NCLS], a2[NCLS];
#pragma unroll
    for (int c = 0; c < NCLS; c++) { a1[c] = 0.0f; a2[c] = 0.0f; }
#pragma unroll
    for (int rr = 0; rr < 16; ++rr) {
        float v  = X[(r0 + rr) * NDIM + k];
        float v2 = v * v;
        int   c  = slab[g * 16 + rr];
#pragma unroll
        for (int cc = 0; cc < NCLS; cc++) {
            bool m = (cc == c);
            a1[cc] += m ? v  : 0.0f;
            a2[cc] += m ? v2 : 0.0f;
        }
    }
#pragma unroll
    for (int cc = 0; cc < NCLS; cc++) {
        red1[g][cc * NDIM + k] = a1[cc];
        red2[g][cc * NDIM + k] = a2[cc];
    }
    __syncthreads();
    // 512 accumulator slots, 256 threads -> 2 slots per thread
#pragma unroll
    for (int q = 0; q < 2; q++) {
        int idx = q * 256 + t;
        float s1 = red1[0][idx] + red1[1][idx] + red1[2][idx] + red1[3][idx];
        float s2 = red2[0][idx] + red2[1][idx] + red2[2][idx] + red2[3][idx];
        atomicAdd(&g_s1[idx], s1);
        atomicAdd(&g_s2[idx], s2);
    }
}

// ---------------- rare path: exact 64-dim evaluation ----------------
__device__ __noinline__ void eval_pair(const float* __restrict__ X,
                                       const int* __restrict__ lab, int i, int j) {
    if (lab[i] == lab[j]) return;       // same-label handled in closed form
    const float4* xi = (const float4*)(X + i * NDIM);
    const float4* xj = (const float4*)(X + j * NDIM);
    float s = 0.0f;
#pragma unroll
    for (int q = 0; q < 16; q++) {
        float4 a = xi[q], b = xj[q];
        float d;
        d = a.x - b.x; s = fmaf(d, d, s);
        d = a.y - b.y; s = fmaf(d, d, s);
        d = a.z - b.z; s = fmaf(d, d, s);
        d = a.w - b.w; s = fmaf(d, d, s);
    }
    if (s < 1.0f) {
        float u = 1.0f - sqrtf(fmaxf(s, 0.0f));
        atomicAdd(&g_neg, 2.0 * (double)u * (double)u);   // unordered -> ordered pairs
    }
}

__device__ __forceinline__ float half_norm8(float4 v0, float4 v1) {
    float s = v0.x * v0.x;
    s = fmaf(v0.y, v0.y, s);
    s = fmaf(v0.z, v0.z, s);
    s = fmaf(v0.w, v0.w, s);
    s = fmaf(v1.x, v1.x, s);
    s = fmaf(v1.y, v1.y, s);
    s = fmaf(v1.z, v1.z, s);
    s = fmaf(v1.w, v1.w, s);
    return 0.5f * s;
}

// ---------------- K2: screen (8-dim dot-form lower bound) + inline eval -------
// grid (64, 16), 128 threads. Block (bj,bi): i in [bi*512,+512), j in [bj*128,+128).
// Keep blocks that can contain j > i pairs: bj >= 4*bi. Blocks with bj >= 4*bi+4
// are fully off-diagonal -> skip the per-pair j>i test.
// Pass test: dot8 - hj > hi - 0.505  <=>  partial d2 over 8 dims < 1.01 (exact LB).
__global__ void __launch_bounds__(128) screen_kernel(const float* __restrict__ X,
                                                     const int* __restrict__ lab) {
    int bi = blockIdx.y, bj = blockIdx.x;
    if (bj < 4 * bi) return;
    int t = threadIdx.x;

    __shared__ float4 sj[TJ][2];
    __shared__ float  smhj[TJ];       // -hj
    const float4* Xv = (const float4*)X;

    int jr = bj * TJ + t;
    float4 j0 = Xv[jr * 16 + 0];
    float4 j1 = Xv[jr * 16 + 1];
    sj[t][0] = j0;
    sj[t][1] = j1;
    smhj[t]  = -half_norm8(j0, j1);

    float4 a[4][2];
    float  ci[4];
    int    ib[4];
#pragma unroll
    for (int r = 0; r < 4; r++) {
        ib[r]   = bi * TI + r * 128 + t;
        a[r][0] = Xv[ib[r] * 16 + 0];
        a[r][1] = Xv[ib[r] * 16 + 1];
        ci[r]   = half_norm8(a[r][0], a[r][1]) - 0.505f;
    }
    __syncthreads();

    bool diag = (bj < 4 * bi + 4);
    if (!diag) {
        // fully off-diagonal: every (i,j) here has j > i
#pragma unroll 4
        for (int j = 0; j < TJ; ++j) {
            float4 b0 = sj[j][0];
            float4 b1 = sj[j][1];
            float mhj = smhj[j];
#pragma unroll
            for (int r = 0; r < 4; r++) {
                float dot = fmaf(a[r][0].x, b0.x, mhj);
                dot = fmaf(a[r][0].y, b0.y, dot);
                dot = fmaf(a[r][0].z, b0.z, dot);
                dot = fmaf(a[r][0].w, b0.w, dot);
                dot = fmaf(a[r][1].x, b1.x, dot);
                dot = fmaf(a[r][1].y, b1.y, dot);
                dot = fmaf(a[r][1].z, b1.z, dot);
                dot = fmaf(a[r][1].w, b1.w, dot);
                if (dot > ci[r]) eval_pair(X, lab, ib[r], bj * TJ + j);
            }
        }
    } else {
#pragma unroll 4
        for (int j = 0; j < TJ; ++j) {
            float4 b0 = sj[j][0];
            float4 b1 = sj[j][1];
            float mhj = smhj[j];
            int    jg = bj * TJ + j;
#pragma unroll
            for (int r = 0; r < 4; r++) {
                float dot = fmaf(a[r][0].x, b0.x, mhj);
                dot = fmaf(a[r][0].y, b0.y, dot);
                dot = fmaf(a[r][0].z, b0.z, dot);
                dot = fmaf(a[r][0].w, b0.w, dot);
                dot = fmaf(a[r][1].x, b1.x, dot);
                dot = fmaf(a[r][1].y, b1.y, dot);
                dot = fmaf(a[r][1].z, b1.z, dot);
                dot = fmaf(a[r][1].w, b1.w, dot);
                if (dot > ci[r] && jg > ib[r]) eval_pair(X, lab, ib[r], jg);
            }
        }
    }
}

// ---------------- K3: finalize (atomic-free histogram + fp64 reduce) ----------
__global__ void __launch_bounds__(512) finalize_kernel(const int* __restrict__ lab,
                                                       float* __restrict__ out) {
    int t = threadIdx.x;                    // t = c*64 + k
    __shared__ int    hcnt[512][NCLS];
    __shared__ int    hist[NCLS];
    __shared__ double red[512];

    // register-based label histogram: 16 labels per thread, no atomics
    int cnt[NCLS];
#pragma unroll
    for (int c = 0; c < NCLS; c++) cnt[c] = 0;
#pragma unroll
    for (int q = 0; q < 16; q++) {
        int c = lab[q * 512 + t];
#pragma unroll
        for (int cc = 0; cc < NCLS; cc++) cnt[cc] += (cc == c) ? 1 : 0;
    }
#pragma unroll
    for (int c = 0; c < NCLS; c++) hcnt[t][c] = cnt[c];
    __syncthreads();
    for (int s = 256; s > 0; s >>= 1) {
        if (t < s) {
#pragma unroll
            for (int c = 0; c < NCLS; c++) hcnt[t][c] += hcnt[t + s][c];
        }
        __syncthreads();
    }
    if (t < NCLS) hist[t] = hcnt[0][t];
    __syncthreads();

    int c = t >> 6;
    double S1 = (double)g_s1[t];
    double S2 = (double)g_s2[t];
    red[t] = (double)hist[c] * S2 - S1 * S1;
    __syncthreads();
    for (int s = 256; s > 0; s >>= 1) {
        if (t < s) red[t] += red[t + s];
        __syncthreads();
    }
    if (t == 0) {
        double pos  = 2.0 * red[0];
        double loss = (pos + g_neg) / ((double)N_PTS * (double)(N_PTS - 1));
        out[0] = (float)loss;
    }
}

extern "C" void kernel_launch(void* const* d_in, const int* in_sizes, int n_in,
                              void* d_out, int out_size) {
    const float* X   = (const float*)d_in[0];
    const int*   lab = (const int*)d_in[1];
    float*       out = (float*)d_out;

    zero_kernel<<<1, 512>>>();
    prep_kernel<<<128, 256>>>(X, lab);
    dim3 g(64, 16);
    screen_kernel<<<g, 128>>>(X, lab);
    finalize_kernel<<<1, 512>>>(lab, out);
}